// round 5
// baseline (speedup 1.0000x reference)
#include <cuda_runtime.h>
#include <math_constants.h>

#define FULL_MASK 0xFFFFFFFFu
#define INF_BITS  0x7f800000u

// x: (32, 2, 513, 2048) fp32. channel 0 = magnitude, channel 1 = phase.
// rows = 32*513 = 16416, row length 2048. One warp per row, no smem.
// Top-32-smallest-squares: per-lane branchless sorted-6 list + REDUX.MIN
// extraction; exact rebuild-on-exhaust (~1.2% of rows).
// R5: regs <=48 -> 10 blocks/SM -> 40 resident warps (was 32) to raise HBM duty.

// Branchless insert of s into sorted list m0<=...<=m5 (keep 6 smallest).
#define INS(sv) do { float s_ = (sv);            \
    m5 = fminf(m5, fmaxf(m4, s_));               \
    m4 = fminf(m4, fmaxf(m3, s_));               \
    m3 = fminf(m3, fmaxf(m2, s_));               \
    m2 = fminf(m2, fmaxf(m1, s_));               \
    m1 = fminf(m1, fmaxf(m0, s_));               \
    m0 = fminf(m0, s_); } while (0)

__global__ __launch_bounds__(128, 10)   // force <=48 regs -> 40 warps/SM
void spectral_sub_kernel(const float* __restrict__ x, float* __restrict__ out)
{
    const int lane = threadIdx.x & 31;
    const int warp = threadIdx.x >> 5;
    const int row  = blockIdx.x * 4 + warp;          // [0, 16416)

    const int b = row / 513;
    const int f = row - b * 513;
    const size_t moff = (size_t)(b * 1026 + f) * 2048;       // ((b*2+0)*513+f)*2048
    const float4* __restrict__ magv = (const float4*)(x + moff);
    const float4* __restrict__ phv  = (const float4*)(x + moff + (size_t)513 * 2048);
    float4* __restrict__ outr = (float4*)(out + moff);
    float4* __restrict__ outi = (float4*)(out + moff + (size_t)513 * 2048);

    // ---- Phase A: per-lane sorted-6 of the squares of this lane's 64 values ----
    float m0 = CUDART_INF_F, m1 = CUDART_INF_F, m2 = CUDART_INF_F,
          m3 = CUDART_INF_F, m4 = CUDART_INF_F, m5 = CUDART_INF_F;

    #pragma unroll
    for (int h = 0; h < 4; ++h) {
        float4 d[4];
        #pragma unroll
        for (int c = 0; c < 4; ++c)                   // 4 LDG.128 batched (MLP=4)
            d[c] = magv[(h * 4 + c) * 32 + lane];
        #pragma unroll
        for (int c = 0; c < 4; ++c) {
            INS(d[c].x * d[c].x);
            INS(d[c].y * d[c].y);
            INS(d[c].z * d[c].z);
            INS(d[c].w * d[c].w);
        }
    }

    // ---- extraction: 32 ascending pops of the warp-wide minimum ----
    // squares >= 0 -> float bits order-isomorphic to u32.
    float sum = 0.0f;
    #pragma unroll 1
    for (int iter = 0; iter < 32; ++iter) {
        unsigned u = __float_as_uint(m0);
        unsigned w = __reduce_min_sync(FULL_MASK, u);     // REDUX.MIN
        sum += __uint_as_float(w);
        unsigned bal = __ballot_sync(FULL_MASK, u == w);  // exactly one pop per iter
        if (lane == __ffs(bal) - 1) {
            m0 = m1; m1 = m2; m2 = m3; m3 = m4; m4 = m5; m5 = CUDART_INF_F;
            if (__float_as_uint(m0) == INF_BITS) {
                // exact rebuild (~1.2% of rows): next-6 smallest of this lane > t.
                const float t = __uint_as_float(w);
                #pragma unroll
                for (int c = 0; c < 16; ++c) {
                    float4 dv = magv[c * 32 + lane];      // L2-hot reload
                    float s;
                    s = dv.x * dv.x; s = (s > t) ? s : CUDART_INF_F; INS(s);
                    s = dv.y * dv.y; s = (s > t) ? s : CUDART_INF_F; INS(s);
                    s = dv.z * dv.z; s = (s > t) ? s : CUDART_INF_F; INS(s);
                    s = dv.w * dv.w; s = (s > t) ? s : CUDART_INF_F; INS(s);
                }
            }
        }
    }
    const float noise = sum * (1.0f / 32.0f);

    // ---- Pass 2: mag re-read (L2-hot) + streamed phase -> real/imag ----
    #pragma unroll
    for (int s = 0; s < 8; ++s) {
        float4 mm[2], ph[2];
        #pragma unroll
        for (int c = 0; c < 2; ++c) {                 // 4 LDGs batched
            mm[c] = magv[(s * 2 + c) * 32 + lane];
            ph[c] = __ldcs(&phv[(s * 2 + c) * 32 + lane]);
        }
        #pragma unroll
        for (int c = 0; c < 2; ++c) {
            float4 re, im;
            float m, sn, cs;
            m = fmaxf(mm[c].x - noise, 0.0f); __sincosf(ph[c].x, &sn, &cs); re.x = m*cs; im.x = m*sn;
            m = fmaxf(mm[c].y - noise, 0.0f); __sincosf(ph[c].y, &sn, &cs); re.y = m*cs; im.y = m*sn;
            m = fmaxf(mm[c].z - noise, 0.0f); __sincosf(ph[c].z, &sn, &cs); re.z = m*cs; im.z = m*sn;
            m = fmaxf(mm[c].w - noise, 0.0f); __sincosf(ph[c].w, &sn, &cs); re.w = m*cs; im.w = m*sn;
            __stcs(&outr[(s * 2 + c) * 32 + lane], re);
            __stcs(&outi[(s * 2 + c) * 32 + lane], im);
        }
    }
}

extern "C" void kernel_launch(void* const* d_in, const int* in_sizes, int n_in,
                              void* d_out, int out_size)
{
    const float* x = (const float*)d_in[0];
    // d_in[1] = n_avg (int32, fixed at 32 for this problem; algorithm specialized for k==32)
    float* out = (float*)d_out;

    // 16416 rows / 4 warps per block
    spectral_sub_kernel<<<4104, 128>>>(x, out);
}

// round 6
// speedup vs baseline: 1.3299x; 1.3299x over previous
#include <cuda_runtime.h>
#include <math_constants.h>

#define FULL_MASK 0xFFFFFFFFu
#define INF_BITS  0x7f800000u

// x: (32, 2, 513, 2048) fp32. channel 0 = magnitude, channel 1 = phase.
// rows = 32*513 = 16416, row length 2048. One warp per row, no smem.
// Top-32-smallest-squares: per-lane branchless sorted-6 lists + REDUX.MIN
// extraction; exact rebuild-on-exhaust (~1.2% of rows).
// R6 = R4 config (32 warps/SM, prefetch, batch-4 pass 2) +
//      phase-A MLP 8 and two independent INS chains (halved serial latency).

// Branchless insert into sorted list a0<=...<=a5 (keep 6 smallest).
#define INS6(a0,a1,a2,a3,a4,a5,sv) do { float s_ = (sv); \
    a5 = fminf(a5, fmaxf(a4, s_));                       \
    a4 = fminf(a4, fmaxf(a3, s_));                       \
    a3 = fminf(a3, fmaxf(a2, s_));                       \
    a2 = fminf(a2, fmaxf(a1, s_));                       \
    a1 = fminf(a1, fmaxf(a0, s_));                       \
    a0 = fminf(a0, s_); } while (0)

#define INSA(sv) INS6(m0,m1,m2,m3,m4,m5,sv)
#define INSB(sv) INS6(n0,n1,n2,n3,n4,n5,sv)

__global__ __launch_bounds__(128, 8)   // <=64 regs -> 8 blocks -> 32 warps/SM
void spectral_sub_kernel(const float* __restrict__ x, float* __restrict__ out)
{
    const int lane = threadIdx.x & 31;
    const int warp = threadIdx.x >> 5;
    const int row  = blockIdx.x * 4 + warp;          // [0, 16416)

    const int b = row / 513;
    const int f = row - b * 513;
    const size_t moff = (size_t)(b * 1026 + f) * 2048;       // ((b*2+0)*513+f)*2048
    const float4* __restrict__ magv = (const float4*)(x + moff);
    const float4* __restrict__ phv  = (const float4*)(x + moff + (size_t)513 * 2048);
    float4* __restrict__ outr = (float4*)(out + moff);
    float4* __restrict__ outi = (float4*)(out + moff + (size_t)513 * 2048);

    // ---- Phase A: two independent per-lane sorted-6 lists over squares ----
    float m0 = CUDART_INF_F, m1 = CUDART_INF_F, m2 = CUDART_INF_F,
          m3 = CUDART_INF_F, m4 = CUDART_INF_F, m5 = CUDART_INF_F;
    float n0 = CUDART_INF_F, n1 = CUDART_INF_F, n2 = CUDART_INF_F,
          n3 = CUDART_INF_F, n4 = CUDART_INF_F, n5 = CUDART_INF_F;

    #pragma unroll
    for (int h = 0; h < 2; ++h) {
        float4 d[8];
        #pragma unroll
        for (int c = 0; c < 8; ++c)                   // 8 LDG.128 batched (MLP=8)
            d[c] = magv[(h * 8 + c) * 32 + lane];
        #pragma unroll
        for (int c = 0; c < 8; c += 2) {
            float4 a = d[c], e = d[c + 1];            // two independent chains
            INSA(a.x * a.x);  INSB(e.x * e.x);
            INSA(a.y * a.y);  INSB(e.y * e.y);
            INSA(a.z * a.z);  INSB(e.z * e.z);
            INSA(a.w * a.w);  INSB(e.w * e.w);
        }
    }
    // merge list B into list A -> A holds this lane's 6 smallest squares
    INSA(n0); INSA(n1); INSA(n2); INSA(n3); INSA(n4); INSA(n5);

    // ---- prefetch pass-2 batch 0 (hidden behind the extraction chain) ----
    float4 pm[4], pp[4];
    #pragma unroll
    for (int c = 0; c < 4; ++c) {
        pm[c] = magv[c * 32 + lane];
        pp[c] = __ldcs(&phv[c * 32 + lane]);
    }

    // ---- extraction: 32 ascending pops of the warp-wide minimum ----
    // squares >= 0 -> float bits order-isomorphic to u32.
    float sum = 0.0f;
    #pragma unroll 1
    for (int iter = 0; iter < 32; ++iter) {
        unsigned u = __float_as_uint(m0);
        unsigned w = __reduce_min_sync(FULL_MASK, u);     // REDUX.MIN
        sum += __uint_as_float(w);
        unsigned bal = __ballot_sync(FULL_MASK, u == w);  // exactly one pop per iter
        if (lane == __ffs(bal) - 1) {
            m0 = m1; m1 = m2; m2 = m3; m3 = m4; m4 = m5; m5 = CUDART_INF_F;
            if (__float_as_uint(m0) == INF_BITS) {
                // exact rebuild (~1.2% of rows): next-6 smallest of this lane > t.
                const float t = __uint_as_float(w);
                #pragma unroll
                for (int c = 0; c < 16; ++c) {
                    float4 dv = magv[c * 32 + lane];      // L2-hot reload
                    float s;
                    s = dv.x * dv.x; s = (s > t) ? s : CUDART_INF_F; INSA(s);
                    s = dv.y * dv.y; s = (s > t) ? s : CUDART_INF_F; INSA(s);
                    s = dv.z * dv.z; s = (s > t) ? s : CUDART_INF_F; INSA(s);
                    s = dv.w * dv.w; s = (s > t) ? s : CUDART_INF_F; INSA(s);
                }
            }
        }
    }
    const float noise = sum * (1.0f / 32.0f);

    // ---- Pass 2: mag re-read (L2-hot) + streamed phase -> real/imag ----
    #pragma unroll
    for (int s = 0; s < 4; ++s) {
        float4 mm[4], ph[4];
        if (s == 0) {
            #pragma unroll
            for (int c = 0; c < 4; ++c) { mm[c] = pm[c]; ph[c] = pp[c]; }
        } else {
            #pragma unroll
            for (int c = 0; c < 4; ++c) {             // 8 LDGs batched (MLP=8)
                mm[c] = magv[(s * 4 + c) * 32 + lane];
                ph[c] = __ldcs(&phv[(s * 4 + c) * 32 + lane]);
            }
        }
        #pragma unroll
        for (int c = 0; c < 4; ++c) {
            float4 re, im;
            float m, sn, cs;
            m = fmaxf(mm[c].x - noise, 0.0f); __sincosf(ph[c].x, &sn, &cs); re.x = m*cs; im.x = m*sn;
            m = fmaxf(mm[c].y - noise, 0.0f); __sincosf(ph[c].y, &sn, &cs); re.y = m*cs; im.y = m*sn;
            m = fmaxf(mm[c].z - noise, 0.0f); __sincosf(ph[c].z, &sn, &cs); re.z = m*cs; im.z = m*sn;
            m = fmaxf(mm[c].w - noise, 0.0f); __sincosf(ph[c].w, &sn, &cs); re.w = m*cs; im.w = m*sn;
            __stcs(&outr[(s * 4 + c) * 32 + lane], re);
            __stcs(&outi[(s * 4 + c) * 32 + lane], im);
        }
    }
}

extern "C" void kernel_launch(void* const* d_in, const int* in_sizes, int n_in,
                              void* d_out, int out_size)
{
    const float* x = (const float*)d_in[0];
    // d_in[1] = n_avg (int32, fixed at 32 for this problem; algorithm specialized for k==32)
    float* out = (float*)d_out;

    // 16416 rows / 4 warps per block
    spectral_sub_kernel<<<4104, 128>>>(x, out);
}